// round 2
// baseline (speedup 1.0000x reference)
#include <cuda_runtime.h>
#include <cstdint>

// Problem constants
#define B  2
#define L  8192
#define D  1024
#define NFFT 16384
#define TPB 512           // threads per FFT block
#define SMEM_BYTES ((NFFT + 4096) * sizeof(float2))  // data + cbuf = 163840

// ---------------- device scratch (no allocs allowed) ----------------
__device__ float  g_xt[(size_t)B * D * L];     // x transposed [B][D][L]
__device__ float  g_ht[(size_t)D * L];         // h transposed [D][L]
__device__ float2 g_hf[(size_t)D * NFFT];      // H spectrum (digit-reversed order)
__device__ float  g_yt[(size_t)B * D * L];     // y transposed [B][D][L]
__device__ float2 g_tw[NFFT / 4];              // W_N^k, k < N/4

// ---------------- complex helpers ----------------
__device__ __forceinline__ float2 cmul(float2 a, float2 b) {
    return make_float2(fmaf(a.x, b.x, -a.y * b.y),
                       fmaf(a.x, b.y,  a.y * b.x));
}
__device__ __forceinline__ float2 cadd(float2 a, float2 b) { return make_float2(a.x + b.x, a.y + b.y); }
__device__ __forceinline__ float2 csub(float2 a, float2 b) { return make_float2(a.x - b.x, a.y - b.y); }

// ---------------- twiddle init ----------------
__global__ void twinit_kernel() {
    int k = blockIdx.x * blockDim.x + threadIdx.x;
    if (k < NFFT / 4) {
        float s, c;
        // angle = -2*pi*k/NFFT  ->  sincospif(-2k/NFFT)
        sincospif(-2.0f * (float)k / (float)NFFT, &s, &c);
        g_tw[k] = make_float2(c, s);
    }
}

// ---------------- tiled transpose: in[R][C] -> out[C][R], batched over z ----------------
__global__ void transpose_kernel(const float* __restrict__ in, float* __restrict__ out,
                                 int R, int C) {
    __shared__ float t[32][33];
    size_t zoff = (size_t)blockIdx.z * (size_t)R * (size_t)C;
    int c = blockIdx.x * 32 + threadIdx.x;
    int rbase = blockIdx.y * 32;
#pragma unroll
    for (int i = threadIdx.y; i < 32; i += 8)
        t[i][threadIdx.x] = in[zoff + (size_t)(rbase + i) * C + c];
    __syncthreads();
    int r = rbase + threadIdx.x;
    int cbase = blockIdx.x * 32;
#pragma unroll
    for (int i = threadIdx.y; i < 32; i += 8)
        out[zoff + (size_t)(cbase + i) * R + r] = t[threadIdx.x][i];
}

// ---------------- in-place radix-4 DIF forward (natural in -> digit-reversed out) ----------------
__device__ __forceinline__ void fft_dif_fwd(float2* data, float2* cbuf, int tid) {
    // stages: len = 16384, 4096, ..., 4   (ls = 14, 12, ..., 2)
    for (int ls = 14; ls >= 2; ls -= 2) {
        const int q  = 1 << (ls - 2);
        const int S  = 1 << (14 - ls);
        __syncthreads();
        for (int j = tid; j < q; j += TPB) cbuf[j] = g_tw[j * S];
        __syncthreads();
#pragma unroll 1
        for (int i = tid; i < (NFFT >> 2); i += TPB) {
            int j = i & (q - 1);
            int g = i >> (ls - 2);
            int base = (g << ls) + j;
            float2 x0 = data[base];
            float2 x1 = data[base + q];
            float2 x2 = data[base + 2 * q];
            float2 x3 = data[base + 3 * q];
            float2 t0 = cadd(x0, x2), t1 = csub(x0, x2);
            float2 t2 = cadd(x1, x3), t3 = csub(x1, x3);
            float2 X0 = cadd(t0, t2);
            float2 X2 = csub(t0, t2);
            float2 X1 = make_float2(t1.x + t3.y, t1.y - t3.x);  // t1 - i*t3
            float2 X3 = make_float2(t1.x - t3.y, t1.y + t3.x);  // t1 + i*t3
            float2 w  = cbuf[j];
            float2 w2 = cmul(w, w);
            float2 w3 = cmul(w2, w);
            data[base]         = X0;
            data[base + q]     = cmul(X1, w);
            data[base + 2 * q] = cmul(X2, w2);
            data[base + 3 * q] = cmul(X3, w3);
        }
    }
    __syncthreads();
}

// ---------------- in-place radix-4 DIT inverse (digit-reversed in -> natural out), unscaled ----------------
__device__ __forceinline__ void fft_dit_inv(float2* data, float2* cbuf, int tid) {
    // stages: len = 4, 16, ..., 16384   (ls = 2, 4, ..., 14)
    for (int ls = 2; ls <= 14; ls += 2) {
        const int q  = 1 << (ls - 2);
        const int S  = 1 << (14 - ls);
        __syncthreads();
        for (int j = tid; j < q; j += TPB) cbuf[j] = g_tw[j * S];
        __syncthreads();
#pragma unroll 1
        for (int i = tid; i < (NFFT >> 2); i += TPB) {
            int j = i & (q - 1);
            int g = i >> (ls - 2);
            int base = (g << ls) + j;
            float2 y0 = data[base];
            float2 x1 = data[base + q];
            float2 x2 = data[base + 2 * q];
            float2 x3 = data[base + 3 * q];
            float2 w  = cbuf[j];
            float2 wc  = make_float2(w.x, -w.y);
            float2 w2c = cmul(wc, wc);
            float2 w3c = cmul(w2c, wc);
            float2 y1 = cmul(x1, wc);
            float2 y2 = cmul(x2, w2c);
            float2 y3 = cmul(x3, w3c);
            float2 t0 = cadd(y0, y2), t1 = csub(y0, y2);
            float2 t2 = cadd(y1, y3), t3 = csub(y1, y3);
            float2 X0 = cadd(t0, t2);
            float2 X2 = csub(t0, t2);
            float2 X1 = make_float2(t1.x - t3.y, t1.y + t3.x);  // t1 + i*t3
            float2 X3 = make_float2(t1.x + t3.y, t1.y - t3.x);  // t1 - i*t3
            data[base]         = X0;
            data[base + q]     = X1;
            data[base + 2 * q] = X2;
            data[base + 3 * q] = X3;
        }
    }
    __syncthreads();
}

// ---------------- H spectrum: one channel per block ----------------
__global__ __launch_bounds__(TPB, 1)
void hfft_kernel() {
    extern __shared__ float2 smem[];
    float2* data = smem;
    float2* cbuf = smem + NFFT;
    const int tid = threadIdx.x;
    const int d   = blockIdx.x;

    const float* __restrict__ hrow = g_ht + (size_t)d * L;
    for (int l = tid; l < L; l += TPB)     data[l] = make_float2(hrow[l], 0.0f);
    for (int l = L + tid; l < NFFT; l += TPB) data[l] = make_float2(0.0f, 0.0f);

    fft_dif_fwd(data, cbuf, tid);

    float2* __restrict__ hf = g_hf + (size_t)d * NFFT;
    for (int k = tid; k < NFFT; k += TPB) hf[k] = data[k];
}

// ---------------- conv: one channel per block, both batches packed re/im ----------------
__global__ __launch_bounds__(TPB, 1)
void conv_kernel(const float* __restrict__ bias) {
    extern __shared__ float2 smem[];
    float2* data = smem;
    float2* cbuf = smem + NFFT;
    const int tid = threadIdx.x;
    const int d   = blockIdx.x;

    const float* __restrict__ x0 = g_xt + (size_t)d * L;            // batch 0
    const float* __restrict__ x1 = g_xt + (size_t)(D + d) * L;      // batch 1
    for (int l = tid; l < L; l += TPB)        data[l] = make_float2(x0[l], x1[l]);
    for (int l = L + tid; l < NFFT; l += TPB) data[l] = make_float2(0.0f, 0.0f);

    fft_dif_fwd(data, cbuf, tid);

    // pointwise multiply in digit-reversed spectral domain
    const float2* __restrict__ hf = g_hf + (size_t)d * NFFT;
    for (int k = tid; k < NFFT; k += TPB) data[k] = cmul(data[k], hf[k]);

    fft_dit_inv(data, cbuf, tid);

    const float invN = 1.0f / (float)NFFT;
    const float bd = bias[d];
    float* __restrict__ y0 = g_yt + (size_t)d * L;
    float* __restrict__ y1 = g_yt + (size_t)(D + d) * L;
    for (int l = tid; l < L; l += TPB) {
        float2 v = data[l];
        y0[l] = fmaf(v.x, invN, bd);   // Re -> batch 0
        y1[l] = fmaf(v.y, invN, bd);   // Im -> batch 1
    }
}

// ---------------- launch ----------------
extern "C" void kernel_launch(void* const* d_in, const int* in_sizes, int n_in,
                              void* d_out, int out_size) {
    const float* x    = (const float*)d_in[0];
    const float* h    = (const float*)d_in[1];
    const float* bias = (const float*)d_in[2];
    float* out = (float*)d_out;

    void *xt_p, *ht_p, *yt_p;
    cudaGetSymbolAddress(&xt_p, g_xt);
    cudaGetSymbolAddress(&ht_p, g_ht);
    cudaGetSymbolAddress(&yt_p, g_yt);

    cudaFuncSetAttribute(hfft_kernel, cudaFuncAttributeMaxDynamicSharedMemorySize, SMEM_BYTES);
    cudaFuncSetAttribute(conv_kernel, cudaFuncAttributeMaxDynamicSharedMemorySize, SMEM_BYTES);

    // 1. twiddles
    twinit_kernel<<<8, 512>>>();
    // 2. transpose x [B][L][D] -> [B][D][L] ; h [L][D] -> [D][L]
    transpose_kernel<<<dim3(D / 32, L / 32, B), dim3(32, 8)>>>(x, (float*)xt_p, L, D);
    transpose_kernel<<<dim3(D / 32, L / 32, 1), dim3(32, 8)>>>(h, (float*)ht_p, L, D);
    // 3. H spectra
    hfft_kernel<<<D, TPB, SMEM_BYTES>>>();
    // 4. packed-batch FFT conv + bias
    conv_kernel<<<D, TPB, SMEM_BYTES>>>(bias);
    // 5. untranspose y [B][D][L] -> [B][L][D]
    transpose_kernel<<<dim3(L / 32, D / 32, B), dim3(32, 8)>>>((const float*)yt_p, out, D, L);
}

// round 3
// speedup vs baseline: 1.4219x; 1.4219x over previous
#include <cuda_runtime.h>
#include <cstdint>

// Problem constants
#define B  2
#define L  8192
#define D  1024
#define NFFT 16384
#define TPB 512
#define NPAD (NFFT + NFFT/16)                 // padded float2 slots = 17408
#define SMEM_BYTES (NPAD * sizeof(float2))    // 139264 B

// ---------------- device scratch ----------------
__device__ float  g_xt[(size_t)B * D * L];
__device__ float  g_ht[(size_t)D * L];
__device__ float2 g_hf[(size_t)D * NFFT];
__device__ float  g_yt[(size_t)B * D * L];
__device__ float2 g_tw[NFFT / 4];             // W_N^k, k < N/4

// ---------------- helpers ----------------
__device__ __forceinline__ int pidx(int a) { return a + (a >> 4); }  // bank-conflict pad

__device__ __forceinline__ float2 cmul(float2 a, float2 b) {
    return make_float2(fmaf(a.x, b.x, -a.y * b.y),
                       fmaf(a.x, b.y,  a.y * b.x));
}
__device__ __forceinline__ float2 cadd(float2 a, float2 b) { return make_float2(a.x + b.x, a.y + b.y); }
__device__ __forceinline__ float2 csub(float2 a, float2 b) { return make_float2(a.x - b.x, a.y - b.y); }

// DIF radix-4 butterfly (twiddles applied by caller on outputs 1..3)
__device__ __forceinline__ void bf4_dif(float2& a0, float2& a1, float2& a2, float2& a3) {
    float2 t0 = cadd(a0, a2), t1 = csub(a0, a2);
    float2 t2 = cadd(a1, a3), t3 = csub(a1, a3);
    a0 = cadd(t0, t2);
    a2 = csub(t0, t2);
    a1 = make_float2(t1.x + t3.y, t1.y - t3.x);  // t1 - i*t3
    a3 = make_float2(t1.x - t3.y, t1.y + t3.x);  // t1 + i*t3
}
// DIT radix-4 butterfly (conj twiddles applied by caller on inputs 1..3)
__device__ __forceinline__ void bf4_dit(float2& a0, float2& a1, float2& a2, float2& a3) {
    float2 t0 = cadd(a0, a2), t1 = csub(a0, a2);
    float2 t2 = cadd(a1, a3), t3 = csub(a1, a3);
    a0 = cadd(t0, t2);
    a2 = csub(t0, t2);
    a1 = make_float2(t1.x - t3.y, t1.y + t3.x);  // t1 + i*t3
    a3 = make_float2(t1.x + t3.y, t1.y - t3.x);  // t1 - i*t3
}

// ---------------- twiddle init ----------------
__global__ void twinit_kernel() {
    int k = blockIdx.x * blockDim.x + threadIdx.x;
    if (k < NFFT / 4) {
        float s, c;
        sincospif(-2.0f * (float)k / (float)NFFT, &s, &c);
        g_tw[k] = make_float2(c, s);
    }
}

// ---------------- tiled transpose: in[R][C] -> out[C][R], batched over z ----------------
__global__ void transpose_kernel(const float* __restrict__ in, float* __restrict__ out,
                                 int R, int C) {
    __shared__ float t[32][33];
    size_t zoff = (size_t)blockIdx.z * (size_t)R * (size_t)C;
    int c = blockIdx.x * 32 + threadIdx.x;
    int rbase = blockIdx.y * 32;
#pragma unroll
    for (int i = threadIdx.y; i < 32; i += 8)
        t[i][threadIdx.x] = in[zoff + (size_t)(rbase + i) * C + c];
    __syncthreads();
    int r = rbase + threadIdx.x;
    int cbase = blockIdx.x * 32;
#pragma unroll
    for (int i = threadIdx.y; i < 32; i += 8)
        out[zoff + (size_t)(cbase + i) * R + r] = t[threadIdx.x][i];
}

// ---------------- forward: combined DIF stages (LS, LS-2) in registers ----------------
template<int LS>
__device__ __forceinline__ void dif_pair(float2* sd, int tid) {
    constexpr int Q2 = 1 << (LS - 4);     // q of stage LS-2
    constexpr int Q  = 1 << (LS - 2);     // q of stage LS
    constexpr int S  = 1 << (14 - LS);
    __syncthreads();
#pragma unroll
    for (int tt = 0; tt < (NFFT / 16) / TPB; ++tt) {
        int t  = tid + tt * TPB;
        int j2 = t & (Q2 - 1);
        int g  = t >> (LS - 4);
        int base = (g << LS) + j2;
        float2 v[4][4];
#pragma unroll
        for (int r = 0; r < 4; r++)
#pragma unroll
            for (int s = 0; s < 4; s++)
                v[r][s] = sd[pidx(base + r * Q2 + s * Q)];
        // level 1 = stage LS: butterfly over s for each r, twiddle idx (j2 + r*Q2)*S
#pragma unroll
        for (int r = 0; r < 4; r++) {
            bf4_dif(v[r][0], v[r][1], v[r][2], v[r][3]);
            float2 w  = g_tw[(j2 + r * Q2) * S];
            float2 w2 = cmul(w, w);
            float2 w3 = cmul(w2, w);
            v[r][1] = cmul(v[r][1], w);
            v[r][2] = cmul(v[r][2], w2);
            v[r][3] = cmul(v[r][3], w3);
        }
        // level 2 = stage LS-2: butterfly over r for each s, twiddle idx j2*4S
        float2 wb  = g_tw[j2 * (S * 4)];
        float2 wb2 = cmul(wb, wb);
        float2 wb3 = cmul(wb2, wb);
#pragma unroll
        for (int s = 0; s < 4; s++) {
            bf4_dif(v[0][s], v[1][s], v[2][s], v[3][s]);
            v[1][s] = cmul(v[1][s], wb);
            v[2][s] = cmul(v[2][s], wb2);
            v[3][s] = cmul(v[3][s], wb3);
        }
#pragma unroll
        for (int r = 0; r < 4; r++)
#pragma unroll
            for (int s = 0; s < 4; s++)
                sd[pidx(base + r * Q2 + s * Q)] = v[r][s];
    }
}

// final DIF stage ls=2 (q=1, twiddle = 1)
__device__ __forceinline__ void dif_last(float2* sd, int tid) {
    __syncthreads();
#pragma unroll
    for (int tt = 0; tt < (NFFT / 4) / TPB; ++tt) {
        int base = (tid + tt * TPB) << 2;
        float2 a0 = sd[pidx(base + 0)];
        float2 a1 = sd[pidx(base + 1)];
        float2 a2 = sd[pidx(base + 2)];
        float2 a3 = sd[pidx(base + 3)];
        bf4_dif(a0, a1, a2, a3);
        sd[pidx(base + 0)] = a0;
        sd[pidx(base + 1)] = a1;
        sd[pidx(base + 2)] = a2;
        sd[pidx(base + 3)] = a3;
    }
}

// ---------------- inverse: first DIT stage ls=2 (q=1, twiddle = 1) ----------------
__device__ __forceinline__ void dit_first(float2* sd, int tid) {
    __syncthreads();
#pragma unroll
    for (int tt = 0; tt < (NFFT / 4) / TPB; ++tt) {
        int base = (tid + tt * TPB) << 2;
        float2 a0 = sd[pidx(base + 0)];
        float2 a1 = sd[pidx(base + 1)];
        float2 a2 = sd[pidx(base + 2)];
        float2 a3 = sd[pidx(base + 3)];
        bf4_dit(a0, a1, a2, a3);
        sd[pidx(base + 0)] = a0;
        sd[pidx(base + 1)] = a1;
        sd[pidx(base + 2)] = a2;
        sd[pidx(base + 3)] = a3;
    }
}

// combined DIT stages (LSA, LSA+2) in registers
template<int LSA>
__device__ __forceinline__ void dit_pair(float2* sd, int tid) {
    constexpr int QA   = 1 << (LSA - 2);
    constexpr int SA   = 1 << (14 - LSA);
    constexpr int QB   = 1 << LSA;        // q of stage LSA+2
    constexpr int SB   = SA >> 2;
    constexpr int LENB = 1 << (LSA + 2);
    __syncthreads();
#pragma unroll
    for (int tt = 0; tt < (NFFT / 16) / TPB; ++tt) {
        int t = tid + tt * TPB;
        int j = t & (QA - 1);
        int G = t >> (LSA - 2);
        int base = G * LENB + j;
        float2 v[4][4];
#pragma unroll
        for (int r = 0; r < 4; r++)
#pragma unroll
            for (int s = 0; s < 4; s++)
                v[r][s] = sd[pidx(base + r * QA + s * QB)];
        // level A = stage LSA: butterfly over r for each s, conj twiddle idx j*SA
        {
            float2 w   = g_tw[j * SA];
            float2 wc  = make_float2(w.x, -w.y);
            float2 wc2 = cmul(wc, wc);
            float2 wc3 = cmul(wc2, wc);
#pragma unroll
            for (int s = 0; s < 4; s++) {
                v[1][s] = cmul(v[1][s], wc);
                v[2][s] = cmul(v[2][s], wc2);
                v[3][s] = cmul(v[3][s], wc3);
                bf4_dit(v[0][s], v[1][s], v[2][s], v[3][s]);
            }
        }
        // level B = stage LSA+2: butterfly over s for each r, conj twiddle idx (j + r*QA)*SB
#pragma unroll
        for (int r = 0; r < 4; r++) {
            float2 w   = g_tw[(j + r * QA) * SB];
            float2 wc  = make_float2(w.x, -w.y);
            float2 wc2 = cmul(wc, wc);
            float2 wc3 = cmul(wc2, wc);
            v[r][1] = cmul(v[r][1], wc);
            v[r][2] = cmul(v[r][2], wc2);
            v[r][3] = cmul(v[r][3], wc3);
            bf4_dit(v[r][0], v[r][1], v[r][2], v[r][3]);
        }
#pragma unroll
        for (int r = 0; r < 4; r++)
#pragma unroll
            for (int s = 0; s < 4; s++)
                sd[pidx(base + r * QA + s * QB)] = v[r][s];
    }
}

__device__ __forceinline__ void fft_fwd(float2* sd, int tid) {
    dif_pair<14>(sd, tid);
    dif_pair<10>(sd, tid);
    dif_pair<6>(sd, tid);
    dif_last(sd, tid);
}
__device__ __forceinline__ void fft_inv(float2* sd, int tid) {
    dit_first(sd, tid);
    dit_pair<4>(sd, tid);
    dit_pair<8>(sd, tid);
    dit_pair<12>(sd, tid);
}

// ---------------- H spectrum: one channel per block ----------------
__global__ __launch_bounds__(TPB, 1)
void hfft_kernel() {
    extern __shared__ float2 sd[];
    const int tid = threadIdx.x;
    const int d   = blockIdx.x;

    const float* __restrict__ hrow = g_ht + (size_t)d * L;
    for (int l = tid; l < L; l += TPB)        sd[pidx(l)] = make_float2(hrow[l], 0.0f);
    for (int l = L + tid; l < NFFT; l += TPB) sd[pidx(l)] = make_float2(0.0f, 0.0f);

    fft_fwd(sd, tid);
    __syncthreads();

    float2* __restrict__ hf = g_hf + (size_t)d * NFFT;
    for (int k = tid; k < NFFT; k += TPB) hf[k] = sd[pidx(k)];
}

// ---------------- conv: one channel per block, both batches packed re/im ----------------
__global__ __launch_bounds__(TPB, 1)
void conv_kernel(const float* __restrict__ bias) {
    extern __shared__ float2 sd[];
    const int tid = threadIdx.x;
    const int d   = blockIdx.x;

    const float* __restrict__ x0 = g_xt + (size_t)d * L;
    const float* __restrict__ x1 = g_xt + (size_t)(D + d) * L;
    for (int l = tid; l < L; l += TPB)        sd[pidx(l)] = make_float2(x0[l], x1[l]);
    for (int l = L + tid; l < NFFT; l += TPB) sd[pidx(l)] = make_float2(0.0f, 0.0f);

    fft_fwd(sd, tid);

    __syncthreads();
    const float2* __restrict__ hf = g_hf + (size_t)d * NFFT;
    for (int k = tid; k < NFFT; k += TPB) sd[pidx(k)] = cmul(sd[pidx(k)], hf[k]);

    fft_inv(sd, tid);
    __syncthreads();

    const float invN = 1.0f / (float)NFFT;
    const float bd = bias[d];
    float* __restrict__ y0 = g_yt + (size_t)d * L;
    float* __restrict__ y1 = g_yt + (size_t)(D + d) * L;
    for (int l = tid; l < L; l += TPB) {
        float2 v = sd[pidx(l)];
        y0[l] = fmaf(v.x, invN, bd);
        y1[l] = fmaf(v.y, invN, bd);
    }
}

// ---------------- launch ----------------
extern "C" void kernel_launch(void* const* d_in, const int* in_sizes, int n_in,
                              void* d_out, int out_size) {
    const float* x    = (const float*)d_in[0];
    const float* h    = (const float*)d_in[1];
    const float* bias = (const float*)d_in[2];
    float* out = (float*)d_out;

    void *xt_p, *ht_p, *yt_p;
    cudaGetSymbolAddress(&xt_p, g_xt);
    cudaGetSymbolAddress(&ht_p, g_ht);
    cudaGetSymbolAddress(&yt_p, g_yt);

    cudaFuncSetAttribute(hfft_kernel, cudaFuncAttributeMaxDynamicSharedMemorySize, SMEM_BYTES);
    cudaFuncSetAttribute(conv_kernel, cudaFuncAttributeMaxDynamicSharedMemorySize, SMEM_BYTES);

    twinit_kernel<<<8, 512>>>();
    transpose_kernel<<<dim3(D / 32, L / 32, B), dim3(32, 8)>>>(x, (float*)xt_p, L, D);
    transpose_kernel<<<dim3(D / 32, L / 32, 1), dim3(32, 8)>>>(h, (float*)ht_p, L, D);
    hfft_kernel<<<D, TPB, SMEM_BYTES>>>();
    conv_kernel<<<D, TPB, SMEM_BYTES>>>(bias);
    transpose_kernel<<<dim3(L / 32, D / 32, B), dim3(32, 8)>>>((const float*)yt_p, out, D, L);
}

// round 4
// speedup vs baseline: 1.4628x; 1.0288x over previous
#include <cuda_runtime.h>
#include <cstdint>

// Problem constants
#define B  2
#define L  8192
#define D  1024
#define NFFT 16384
#define TPB 1024
#define NPAD (NFFT + NFFT/16)                 // padded float2 slots = 17408
#define SMEM_BYTES (NPAD * sizeof(float2))    // 139264 B

// ---------------- device scratch ----------------
__device__ float  g_xt[(size_t)B * D * L];
__device__ float  g_ht[(size_t)D * L];
__device__ float2 g_hf[(size_t)D * NFFT];
__device__ float  g_yt[(size_t)B * D * L];
__device__ float2 g_tw[NFFT / 4];             // W_N^k, k < N/4

// ---------------- helpers ----------------
__device__ __forceinline__ int pidx(int a) { return a + (a >> 4); }  // bank-conflict pad

__device__ __forceinline__ float2 cmul(float2 a, float2 b) {
    return make_float2(fmaf(a.x, b.x, -a.y * b.y),
                       fmaf(a.x, b.y,  a.y * b.x));
}
__device__ __forceinline__ float2 cadd(float2 a, float2 b) { return make_float2(a.x + b.x, a.y + b.y); }
__device__ __forceinline__ float2 csub(float2 a, float2 b) { return make_float2(a.x - b.x, a.y - b.y); }

// DIF radix-4 butterfly (twiddles applied by caller on outputs 1..3)
__device__ __forceinline__ void bf4_dif(float2& a0, float2& a1, float2& a2, float2& a3) {
    float2 t0 = cadd(a0, a2), t1 = csub(a0, a2);
    float2 t2 = cadd(a1, a3), t3 = csub(a1, a3);
    a0 = cadd(t0, t2);
    a2 = csub(t0, t2);
    a1 = make_float2(t1.x + t3.y, t1.y - t3.x);  // t1 - i*t3
    a3 = make_float2(t1.x - t3.y, t1.y + t3.x);  // t1 + i*t3
}
// DIT radix-4 butterfly (conj twiddles applied by caller on inputs 1..3)
__device__ __forceinline__ void bf4_dit(float2& a0, float2& a1, float2& a2, float2& a3) {
    float2 t0 = cadd(a0, a2), t1 = csub(a0, a2);
    float2 t2 = cadd(a1, a3), t3 = csub(a1, a3);
    a0 = cadd(t0, t2);
    a2 = csub(t0, t2);
    a1 = make_float2(t1.x - t3.y, t1.y + t3.x);  // t1 + i*t3
    a3 = make_float2(t1.x + t3.y, t1.y - t3.x);  // t1 - i*t3
}

// ---------------- twiddle init ----------------
__global__ void twinit_kernel() {
    int k = blockIdx.x * blockDim.x + threadIdx.x;
    if (k < NFFT / 4) {
        float s, c;
        sincospif(-2.0f * (float)k / (float)NFFT, &s, &c);
        g_tw[k] = make_float2(c, s);
    }
}

// ---------------- tiled transpose: in[R][C] -> out[C][R], batched over z ----------------
__global__ void transpose_kernel(const float* __restrict__ in, float* __restrict__ out,
                                 int R, int C) {
    __shared__ float t[32][33];
    size_t zoff = (size_t)blockIdx.z * (size_t)R * (size_t)C;
    int c = blockIdx.x * 32 + threadIdx.x;
    int rbase = blockIdx.y * 32;
#pragma unroll
    for (int i = threadIdx.y; i < 32; i += 8)
        t[i][threadIdx.x] = in[zoff + (size_t)(rbase + i) * C + c];
    __syncthreads();
    int r = rbase + threadIdx.x;
    int cbase = blockIdx.x * 32;
#pragma unroll
    for (int i = threadIdx.y; i < 32; i += 8)
        out[zoff + (size_t)(cbase + i) * R + r] = t[threadIdx.x][i];
}

// ---------------- forward: combined DIF stages (LS, LS-2) in registers ----------------
// TPB == NFFT/16: each thread owns exactly one radix-16 group.
template<int LS>
__device__ __forceinline__ void dif_pair(float2* sd, int tid) {
    constexpr int Q2 = 1 << (LS - 4);     // q of stage LS-2
    constexpr int Q  = 1 << (LS - 2);     // q of stage LS
    constexpr int S  = 1 << (14 - LS);
    __syncthreads();
    int j2 = tid & (Q2 - 1);
    int g  = tid >> (LS - 4);
    int base = (g << LS) + j2;
    float2 v[4][4];
#pragma unroll
    for (int r = 0; r < 4; r++)
#pragma unroll
        for (int s = 0; s < 4; s++)
            v[r][s] = sd[pidx(base + r * Q2 + s * Q)];
    // level 1 = stage LS: butterfly over s for each r, twiddle idx (j2 + r*Q2)*S
#pragma unroll
    for (int r = 0; r < 4; r++) {
        bf4_dif(v[r][0], v[r][1], v[r][2], v[r][3]);
        float2 w  = g_tw[(j2 + r * Q2) * S];
        float2 w2 = cmul(w, w);
        float2 w3 = cmul(w2, w);
        v[r][1] = cmul(v[r][1], w);
        v[r][2] = cmul(v[r][2], w2);
        v[r][3] = cmul(v[r][3], w3);
    }
    // level 2 = stage LS-2: butterfly over r for each s, twiddle idx j2*4S
    float2 wb  = g_tw[j2 * (S * 4)];
    float2 wb2 = cmul(wb, wb);
    float2 wb3 = cmul(wb2, wb);
#pragma unroll
    for (int s = 0; s < 4; s++) {
        bf4_dif(v[0][s], v[1][s], v[2][s], v[3][s]);
        v[1][s] = cmul(v[1][s], wb);
        v[2][s] = cmul(v[2][s], wb2);
        v[3][s] = cmul(v[3][s], wb3);
    }
#pragma unroll
    for (int r = 0; r < 4; r++)
#pragma unroll
        for (int s = 0; s < 4; s++)
            sd[pidx(base + r * Q2 + s * Q)] = v[r][s];
}

// final DIF stage ls=2 (q=1, twiddle = 1)
__device__ __forceinline__ void dif_last(float2* sd, int tid) {
    __syncthreads();
#pragma unroll
    for (int tt = 0; tt < (NFFT / 4) / TPB; ++tt) {
        int base = (tid + tt * TPB) << 2;
        float2 a0 = sd[pidx(base + 0)];
        float2 a1 = sd[pidx(base + 1)];
        float2 a2 = sd[pidx(base + 2)];
        float2 a3 = sd[pidx(base + 3)];
        bf4_dif(a0, a1, a2, a3);
        sd[pidx(base + 0)] = a0;
        sd[pidx(base + 1)] = a1;
        sd[pidx(base + 2)] = a2;
        sd[pidx(base + 3)] = a3;
    }
}

// ---------------- inverse: first DIT stage ls=2 (q=1, twiddle = 1) ----------------
__device__ __forceinline__ void dit_first(float2* sd, int tid) {
    __syncthreads();
#pragma unroll
    for (int tt = 0; tt < (NFFT / 4) / TPB; ++tt) {
        int base = (tid + tt * TPB) << 2;
        float2 a0 = sd[pidx(base + 0)];
        float2 a1 = sd[pidx(base + 1)];
        float2 a2 = sd[pidx(base + 2)];
        float2 a3 = sd[pidx(base + 3)];
        bf4_dit(a0, a1, a2, a3);
        sd[pidx(base + 0)] = a0;
        sd[pidx(base + 1)] = a1;
        sd[pidx(base + 2)] = a2;
        sd[pidx(base + 3)] = a3;
    }
}

// combined DIT stages (LSA, LSA+2) in registers
template<int LSA>
__device__ __forceinline__ void dit_pair(float2* sd, int tid) {
    constexpr int QA   = 1 << (LSA - 2);
    constexpr int SA   = 1 << (14 - LSA);
    constexpr int QB   = 1 << LSA;        // q of stage LSA+2
    constexpr int SB   = SA >> 2;
    constexpr int LENB = 1 << (LSA + 2);
    __syncthreads();
    int j = tid & (QA - 1);
    int G = tid >> (LSA - 2);
    int base = G * LENB + j;
    float2 v[4][4];
#pragma unroll
    for (int r = 0; r < 4; r++)
#pragma unroll
        for (int s = 0; s < 4; s++)
            v[r][s] = sd[pidx(base + r * QA + s * QB)];
    // level A = stage LSA: butterfly over r for each s, conj twiddle idx j*SA
    {
        float2 w   = g_tw[j * SA];
        float2 wc  = make_float2(w.x, -w.y);
        float2 wc2 = cmul(wc, wc);
        float2 wc3 = cmul(wc2, wc);
#pragma unroll
        for (int s = 0; s < 4; s++) {
            v[1][s] = cmul(v[1][s], wc);
            v[2][s] = cmul(v[2][s], wc2);
            v[3][s] = cmul(v[3][s], wc3);
            bf4_dit(v[0][s], v[1][s], v[2][s], v[3][s]);
        }
    }
    // level B = stage LSA+2: butterfly over s for each r, conj twiddle idx (j + r*QA)*SB
#pragma unroll
    for (int r = 0; r < 4; r++) {
        float2 w   = g_tw[(j + r * QA) * SB];
        float2 wc  = make_float2(w.x, -w.y);
        float2 wc2 = cmul(wc, wc);
        float2 wc3 = cmul(wc2, wc);
        v[r][1] = cmul(v[r][1], wc);
        v[r][2] = cmul(v[r][2], wc2);
        v[r][3] = cmul(v[r][3], wc3);
        bf4_dit(v[r][0], v[r][1], v[r][2], v[r][3]);
    }
#pragma unroll
    for (int r = 0; r < 4; r++)
#pragma unroll
        for (int s = 0; s < 4; s++)
            sd[pidx(base + r * QA + s * QB)] = v[r][s];
}

__device__ __forceinline__ void fft_fwd(float2* sd, int tid) {
    dif_pair<14>(sd, tid);
    dif_pair<10>(sd, tid);
    dif_pair<6>(sd, tid);
    dif_last(sd, tid);
}
__device__ __forceinline__ void fft_inv(float2* sd, int tid) {
    dit_first(sd, tid);
    dit_pair<4>(sd, tid);
    dit_pair<8>(sd, tid);
    dit_pair<12>(sd, tid);
}

// ---------------- H spectrum: one channel per block ----------------
__global__ __launch_bounds__(TPB, 1)
void hfft_kernel() {
    extern __shared__ float2 sd[];
    const int tid = threadIdx.x;
    const int d   = blockIdx.x;

    const float* __restrict__ hrow = g_ht + (size_t)d * L;
    for (int l = tid; l < L; l += TPB)        sd[pidx(l)] = make_float2(hrow[l], 0.0f);
    for (int l = L + tid; l < NFFT; l += TPB) sd[pidx(l)] = make_float2(0.0f, 0.0f);

    fft_fwd(sd, tid);
    __syncthreads();

    float2* __restrict__ hf = g_hf + (size_t)d * NFFT;
    for (int k = tid; k < NFFT; k += TPB) hf[k] = sd[pidx(k)];
}

// ---------------- conv: one channel per block, both batches packed re/im ----------------
__global__ __launch_bounds__(TPB, 1)
void conv_kernel(const float* __restrict__ bias) {
    extern __shared__ float2 sd[];
    const int tid = threadIdx.x;
    const int d   = blockIdx.x;

    const float* __restrict__ x0 = g_xt + (size_t)d * L;
    const float* __restrict__ x1 = g_xt + (size_t)(D + d) * L;
    for (int l = tid; l < L; l += TPB)        sd[pidx(l)] = make_float2(x0[l], x1[l]);
    for (int l = L + tid; l < NFFT; l += TPB) sd[pidx(l)] = make_float2(0.0f, 0.0f);

    fft_fwd(sd, tid);

    __syncthreads();
    const float2* __restrict__ hf = g_hf + (size_t)d * NFFT;
    for (int k = tid; k < NFFT; k += TPB) sd[pidx(k)] = cmul(sd[pidx(k)], hf[k]);

    fft_inv(sd, tid);
    __syncthreads();

    const float invN = 1.0f / (float)NFFT;
    const float bd = bias[d];
    float* __restrict__ y0 = g_yt + (size_t)d * L;
    float* __restrict__ y1 = g_yt + (size_t)(D + d) * L;
    for (int l = tid; l < L; l += TPB) {
        float2 v = sd[pidx(l)];
        y0[l] = fmaf(v.x, invN, bd);
        y1[l] = fmaf(v.y, invN, bd);
    }
}

// ---------------- launch ----------------
extern "C" void kernel_launch(void* const* d_in, const int* in_sizes, int n_in,
                              void* d_out, int out_size) {
    const float* x    = (const float*)d_in[0];
    const float* h    = (const float*)d_in[1];
    const float* bias = (const float*)d_in[2];
    float* out = (float*)d_out;

    void *xt_p, *ht_p, *yt_p;
    cudaGetSymbolAddress(&xt_p, g_xt);
    cudaGetSymbolAddress(&ht_p, g_ht);
    cudaGetSymbolAddress(&yt_p, g_yt);

    cudaFuncSetAttribute(hfft_kernel, cudaFuncAttributeMaxDynamicSharedMemorySize, SMEM_BYTES);
    cudaFuncSetAttribute(conv_kernel, cudaFuncAttributeMaxDynamicSharedMemorySize, SMEM_BYTES);

    twinit_kernel<<<8, 512>>>();
    transpose_kernel<<<dim3(D / 32, L / 32, B), dim3(32, 8)>>>(x, (float*)xt_p, L, D);
    transpose_kernel<<<dim3(D / 32, L / 32, 1), dim3(32, 8)>>>(h, (float*)ht_p, L, D);
    hfft_kernel<<<D, TPB, SMEM_BYTES>>>();
    conv_kernel<<<D, TPB, SMEM_BYTES>>>(bias);
    transpose_kernel<<<dim3(L / 32, D / 32, B), dim3(32, 8)>>>((const float*)yt_p, out, D, L);
}